// round 7
// baseline (speedup 1.0000x reference)
#include <cuda_runtime.h>
#include <math.h>

// ---------------- problem constants ----------------
#define BB 16
#define SS 1024
#define LL 512
#define DD 1024
#define HH 8
#define DHH 128
#define WDD 256

#define MQ   (BB*LL)    // 8192
#define MKV  (BB*SS)    // 16384
#define DPW  (DD+WDD)   // 1280
#define OFF2 (MQ*DD)    // offset of second output tensor in d_out

// ---------------- scratch (__device__ globals; no allocs allowed) ----------------
__device__ float g_Q[MQ*DD];         // 32 MB
__device__ float g_K[MKV*DD];        // 64 MB
__device__ float g_V[MKV*DD];        // 64 MB
__device__ float g_ctx[MQ*DD];       // 32 MB
__device__ float g_concat[MQ*DPW];   // 40 MB
__device__ int   g_cnt[BB*LL];
__device__ int   g_listF[MQ*SS];     // 32 MB (per (b,l): aligned source positions)
__device__ int   g_to_sem[MQ];       // normalized int32 index arrays
__device__ int   g_to_semty[MQ];
__device__ int   g_sem_syn[BB*SS];

// ---------------- index normalization (int64-vs-int32 robust) ----------------
// Reference declares indices int64, but JAX without x64 silently emits int32.
// Runtime detect: for int64 arrays of small non-negative values every odd
// 32-bit word is zero; for int32 values in [0,1024) the odds of 64 odd words
// all being zero are ~2^-640.
__global__ void normalize_idx_kernel(const void* __restrict__ src, int n,
                                     int* __restrict__ dst) {
    __shared__ int is64_s;
    if (threadIdx.x == 0) {
        const int* w = (const int*)src;
        int orv = 0;
        #pragma unroll
        for (int i = 1; i < 128; i += 2) orv |= w[i];   // n >= 8192 elements in all cases
        is64_s = (orv == 0) ? 1 : 0;
    }
    __syncthreads();
    int is64 = is64_s;
    int i = blockIdx.x * blockDim.x + threadIdx.x;
    if (i < n) {
        dst[i] = is64 ? (int)((const long long*)src)[i]
                      : ((const int*)src)[i];
    }
}

// ---------------- small kernels ----------------
__global__ void clear_cnt_kernel() {
    int i = blockIdx.x * blockDim.x + threadIdx.x;
    if (i < BB*LL) g_cnt[i] = 0;
}

__global__ void build_lists_kernel() {
    int i = blockIdx.x * blockDim.x + threadIdx.x;   // 0..B*S-1
    if (i >= BB*SS) return;
    int v = g_sem_syn[i];
    if (v >= 1 && v <= LL) {
        int b = i >> 10;             // /S
        int s = i & (SS-1);
        int slot = b*LL + (v - 1);
        int p = atomicAdd(&g_cnt[slot], 1);
        g_listF[slot*SS + p] = s;
    }
}

// fill type-embedding part of concat buffer
__global__ void type_fill_kernel(const float* __restrict__ type_emb) {
    int m = blockIdx.x;
    int t = g_to_semty[m];
    const float4* ip = (const float4*)(type_emb + (size_t)t * WDD);
    float4* op = (float4*)(g_concat + (size_t)m * DPW + DD);
    op[threadIdx.x] = ip[threadIdx.x];  // 64 threads x float4 = 256 floats
}

// write root rows of second output
__global__ void root_fill_kernel(float* __restrict__ out2, const float* __restrict__ bias_root) {
    int b = blockIdx.x;         // 0..15
    int n = threadIdx.x;        // 0..1023
    out2[(size_t)b * (LL+1) * DD + n] = bias_root[n];
}

// ---------------- SGEMM: C = (A[M,K] * W[N,K]^T + bias[n]) * scale ----------------
// 128x128 tile, bk=8, 256 threads, 8x8 per thread, double-buffered smem.
// Both A and W rows are K-contiguous -> identical coalesced load pattern.
// GATHER: A row r is taken from A[(r>>9)*SS + g_to_sem[r], :] (to_sem gather fused).
// DUAL: additionally scatter C rows into C2 at [(b*513 + l + 1)*1024 + n].
template<bool DUAL, bool GATHER>
__global__ void __launch_bounds__(256)
sgemm_kernel(const float* __restrict__ A, int lda,
             const float* __restrict__ W, int ldw,
             const float* __restrict__ bias, float scale,
             float* __restrict__ C, int ldc,
             float* __restrict__ C2, int K) {
    __shared__ float As[2][8][128];
    __shared__ float Bs[2][8][128];

    int tid = threadIdx.x;
    int bx = blockIdx.x, by = blockIdx.y;
    int tx = tid & 15, ty = tid >> 4;
    int lr = tid >> 1;            // tile row this thread loads (0..127)
    int lk = (tid & 1) * 4;       // k offset within tile (0 or 4)

    const float* Aptr;
    {
        int arow = by * 128 + lr;
        if (GATHER) {
            int b = arow >> 9;
            int src = g_to_sem[arow];
            Aptr = A + ((size_t)(b * SS + src)) * lda + lk;
        } else {
            Aptr = A + (size_t)arow * lda + lk;
        }
    }
    const float* Bptr = W + (size_t)(bx * 128 + lr) * ldw + lk;

    float acc[8][8];
    #pragma unroll
    for (int i = 0; i < 8; i++)
        #pragma unroll
        for (int j = 0; j < 8; j++) acc[i][j] = 0.f;

    // prefetch first tile into registers
    float4 av = *(const float4*)Aptr;
    float4 bv = *(const float4*)Bptr;

    int buf = 0;
    for (int kt = 0; kt < K; kt += 8) {
        As[buf][lk+0][lr] = av.x; As[buf][lk+1][lr] = av.y;
        As[buf][lk+2][lr] = av.z; As[buf][lk+3][lr] = av.w;
        Bs[buf][lk+0][lr] = bv.x; Bs[buf][lk+1][lr] = bv.y;
        Bs[buf][lk+2][lr] = bv.z; Bs[buf][lk+3][lr] = bv.w;
        __syncthreads();

        if (kt + 8 < K) {                   // prefetch next tile during compute
            av = *(const float4*)(Aptr + kt + 8);
            bv = *(const float4*)(Bptr + kt + 8);
        }

        #pragma unroll
        for (int k = 0; k < 8; k++) {
            float a0[4], a1[4], b0[4], b1[4];
            *(float4*)a0 = *(const float4*)&As[buf][k][ty*4];
            *(float4*)a1 = *(const float4*)&As[buf][k][64 + ty*4];
            *(float4*)b0 = *(const float4*)&Bs[buf][k][tx*4];
            *(float4*)b1 = *(const float4*)&Bs[buf][k][64 + tx*4];
            #pragma unroll
            for (int i = 0; i < 4; i++)
                #pragma unroll
                for (int j = 0; j < 4; j++) {
                    acc[i  ][j  ] += a0[i] * b0[j];
                    acc[i  ][j+4] += a0[i] * b1[j];
                    acc[i+4][j  ] += a1[i] * b0[j];
                    acc[i+4][j+4] += a1[i] * b1[j];
                }
        }
        buf ^= 1;
        // No trailing barrier: buffer `buf` is rewritten only two iterations
        // later; the intervening __syncthreads() (reached by every thread only
        // after finishing this compute) orders that rewrite.
    }

    int row0 = by * 128, col0 = bx * 128;
    #pragma unroll
    for (int i = 0; i < 8; i++) {
        int r = row0 + ((i < 4) ? (ty*4 + i) : (64 + ty*4 + i - 4));
        #pragma unroll
        for (int j = 0; j < 8; j++) {
            int c = col0 + ((j < 4) ? (tx*4 + j) : (64 + tx*4 + j - 4));
            float v = (acc[i][j] + bias[c]) * scale;
            C[(size_t)r * ldc + c] = v;
            if (DUAL) {
                int b = r >> 9, l = r & 511;
                C2[((size_t)b * (LL+1) + l + 1) * DD + c] = v;
            }
        }
    }
}

// ---------------- sparse masked attention ----------------
// grid: MQ blocks, 256 threads (8 warps = 8 heads). Warp h handles head h; lane
// holds 4 contiguous dims. Online softmax over the allowed key set (avg ~3 keys:
// positions s with sem_syn[b,s]==l+1, plus the self position to_sem[b,l]).
__global__ void __launch_bounds__(256)
attn_kernel() {
    int m = blockIdx.x;                // (b,l)
    int b = m >> 9, l = m & 511;
    int h = threadIdx.x >> 5;
    int lane = threadIdx.x & 31;

    const float* qp = g_Q + (size_t)m * DD + h * DHH + lane * 4;
    float4 q = *(const float4*)qp;

    int s0 = g_to_sem[m];
    int cnt = g_cnt[m];
    bool addSelf = (g_sem_syn[b * SS + s0] != l + 1);

    float mmax = -1e30f, lsum = 0.f;
    float4 acc = make_float4(0.f, 0.f, 0.f, 0.f);

    int start = addSelf ? -1 : 0;
    for (int i = start; i < cnt; i++) {
        int s = (i < 0) ? s0 : g_listF[(size_t)m * SS + i];
        size_t base = ((size_t)(b * SS + s)) * DD + h * DHH + lane * 4;
        float4 kv = *(const float4*)(g_K + base);
        float dot = q.x*kv.x + q.y*kv.y + q.z*kv.z + q.w*kv.w;
        #pragma unroll
        for (int off = 16; off > 0; off >>= 1)
            dot += __shfl_xor_sync(0xffffffffu, dot, off);

        float newm = fmaxf(mmax, dot);
        float corr = __expf(mmax - newm);   // first iter: exp(-huge) = 0
        float p = __expf(dot - newm);
        lsum = lsum * corr + p;

        float4 vv = *(const float4*)(g_V + base);
        acc.x = acc.x * corr + p * vv.x;
        acc.y = acc.y * corr + p * vv.y;
        acc.z = acc.z * corr + p * vv.z;
        acc.w = acc.w * corr + p * vv.w;
        mmax = newm;
    }

    float inv = 1.f / lsum;
    float4 outv = make_float4(acc.x*inv, acc.y*inv, acc.z*inv, acc.w*inv);
    *(float4*)(g_ctx + (size_t)m * DD + h * DHH + lane * 4) = outv;
}

// ---------------- launch ----------------
extern "C" void kernel_launch(void* const* d_in, const int* in_sizes, int n_in,
                              void* d_out, int out_size) {
    const float* enc       = (const float*)d_in[0];
    const void*  to_sem    = d_in[1];
    const void*  to_semty  = d_in[2];
    const void*  sem_syn   = d_in[3];
    const float* wq = (const float*)d_in[4];
    const float* bq = (const float*)d_in[5];
    const float* wk = (const float*)d_in[6];
    const float* bk = (const float*)d_in[7];
    const float* wv = (const float*)d_in[8];
    const float* bv = (const float*)d_in[9];
    const float* wo = (const float*)d_in[10];
    const float* bo = (const float*)d_in[11];
    const float* type_emb  = (const float*)d_in[12];
    const float* w_proj    = (const float*)d_in[13];
    const float* b_proj    = (const float*)d_in[14];
    const float* bias_root = (const float*)d_in[15];

    float* out = (float*)d_out;

    float *p_Q, *p_K, *p_V, *p_ctx, *p_concat;
    int *p_to_sem, *p_to_semty, *p_sem_syn;
    cudaGetSymbolAddress((void**)&p_Q, g_Q);
    cudaGetSymbolAddress((void**)&p_K, g_K);
    cudaGetSymbolAddress((void**)&p_V, g_V);
    cudaGetSymbolAddress((void**)&p_ctx, g_ctx);
    cudaGetSymbolAddress((void**)&p_concat, g_concat);
    cudaGetSymbolAddress((void**)&p_to_sem, g_to_sem);
    cudaGetSymbolAddress((void**)&p_to_semty, g_to_semty);
    cudaGetSymbolAddress((void**)&p_sem_syn, g_sem_syn);

    const float qscale = 0.08838834764831845f;  // 1/sqrt(128)

    // 0) normalize index dtypes (int64 or int32 -> int32 scratch)
    normalize_idx_kernel<<<(MQ + 255)/256, 256>>>(to_sem, MQ, p_to_sem);
    normalize_idx_kernel<<<(MQ + 255)/256, 256>>>(to_semty, MQ, p_to_semty);
    normalize_idx_kernel<<<(BB*SS + 255)/256, 256>>>(sem_syn, BB*SS, p_sem_syn);

    // 1) mask lists
    clear_cnt_kernel<<<(BB*LL + 255)/256, 256>>>();
    build_lists_kernel<<<(BB*SS + 255)/256, 256>>>();

    // 2) projections (to_sem row gather fused into the Q GEMM's A loads)
    sgemm_kernel<false, true><<<dim3(DD/128, MQ/128), 256>>>(
        enc, DD, wq, DD, bq, qscale, p_Q, DD, nullptr, DD);
    sgemm_kernel<false, false><<<dim3(DD/128, MKV/128), 256>>>(
        enc, DD, wk, DD, bk, 1.f, p_K, DD, nullptr, DD);
    sgemm_kernel<false, false><<<dim3(DD/128, MKV/128), 256>>>(
        enc, DD, wv, DD, bv, 1.f, p_V, DD, nullptr, DD);

    // 3) sparse masked attention
    attn_kernel<<<MQ, 256>>>();

    // 4) output projection -> first 1024 cols of concat buffer
    sgemm_kernel<false, false><<<dim3(DD/128, MQ/128), 256>>>(
        p_ctx, DD, wo, DD, bo, 1.f, p_concat, DPW, nullptr, DD);

    // 5) type embedding -> cols [1024,1280) of concat buffer
    type_fill_kernel<<<MQ, 64>>>(type_emb);

    // 6) final projection; epilogue writes both output tensors
    sgemm_kernel<true, false><<<dim3(DD/128, MQ/128), 256>>>(
        p_concat, DPW, w_proj, DPW, b_proj, 1.f, out, DD, out + OFF2, DPW);

    // 7) root rows of second output
    root_fill_kernel<<<BB, DD>>>(out + OFF2, bias_root);
}

// round 8
// speedup vs baseline: 1.8345x; 1.8345x over previous
#include <cuda_runtime.h>
#include <cuda_bf16.h>
#include <math.h>
#include <stdint.h>

// ---------------- problem constants ----------------
#define BB 16
#define SS 1024
#define LL 512
#define DD 1024
#define HH 8
#define DHH 128
#define WDD 256

#define MQ   (BB*LL)    // 8192
#define MKV  (BB*SS)    // 16384
#define DPW  (DD+WDD)   // 1280
#define OFF2 (MQ*DD)    // offset of second output tensor in d_out

// ---------------- scratch (__device__ globals; no allocs allowed) ----------------
__device__ float g_Q[MQ*DD];
__device__ float g_K[MKV*DD];
__device__ float g_V[MKV*DD];
__device__ float g_ctx[MQ*DD];
__device__ float g_concat[MQ*DPW];
__device__ int   g_cnt[BB*LL];
__device__ int   g_listF[MQ*SS];
__device__ int   g_to_sem[MQ];
__device__ int   g_to_semty[MQ];
__device__ int   g_sem_syn[BB*SS];

// ---------------- index normalization (int64-vs-int32 robust) ----------------
__global__ void normalize_idx_kernel(const void* __restrict__ src, int n,
                                     int* __restrict__ dst) {
    __shared__ int is64_s;
    if (threadIdx.x == 0) {
        const int* w = (const int*)src;
        int orv = 0;
        #pragma unroll
        for (int i = 1; i < 128; i += 2) orv |= w[i];
        is64_s = (orv == 0) ? 1 : 0;
    }
    __syncthreads();
    int is64 = is64_s;
    int i = blockIdx.x * blockDim.x + threadIdx.x;
    if (i < n) {
        dst[i] = is64 ? (int)((const long long*)src)[i]
                      : ((const int*)src)[i];
    }
}

// ---------------- small kernels ----------------
__global__ void clear_cnt_kernel() {
    int i = blockIdx.x * blockDim.x + threadIdx.x;
    if (i < BB*LL) g_cnt[i] = 0;
}

__global__ void build_lists_kernel() {
    int i = blockIdx.x * blockDim.x + threadIdx.x;
    if (i >= BB*SS) return;
    int v = g_sem_syn[i];
    if (v >= 1 && v <= LL) {
        int b = i >> 10;
        int s = i & (SS-1);
        int slot = b*LL + (v - 1);
        int p = atomicAdd(&g_cnt[slot], 1);
        g_listF[slot*SS + p] = s;
    }
}

__global__ void type_fill_kernel(const float* __restrict__ type_emb) {
    int m = blockIdx.x;
    int t = g_to_semty[m];
    const float4* ip = (const float4*)(type_emb + (size_t)t * WDD);
    float4* op = (float4*)(g_concat + (size_t)m * DPW + DD);
    op[threadIdx.x] = ip[threadIdx.x];
}

__global__ void root_fill_kernel(float* __restrict__ out2, const float* __restrict__ bias_root) {
    int b = blockIdx.x;
    int n = threadIdx.x;
    out2[(size_t)b * (LL+1) * DD + n] = bias_root[n];
}

// ---------------- tensor-core helpers ----------------
__device__ __forceinline__ void ldsm4(uint32_t* r, uint32_t saddr) {
    asm volatile("ldmatrix.sync.aligned.m8n8.x4.shared.b16 {%0,%1,%2,%3}, [%4];"
        : "=r"(r[0]), "=r"(r[1]), "=r"(r[2]), "=r"(r[3]) : "r"(saddr));
}
__device__ __forceinline__ void ldsm2(uint32_t* r, uint32_t saddr) {
    asm volatile("ldmatrix.sync.aligned.m8n8.x2.shared.b16 {%0,%1}, [%2];"
        : "=r"(r[0]), "=r"(r[1]) : "r"(saddr));
}
__device__ __forceinline__ void mma16816(float* c, const uint32_t* a, const uint32_t* b) {
    asm volatile("mma.sync.aligned.m16n8k16.row.col.f32.bf16.bf16.f32 "
        "{%0,%1,%2,%3}, {%4,%5,%6,%7}, {%8,%9}, {%0,%1,%2,%3};"
        : "+f"(c[0]), "+f"(c[1]), "+f"(c[2]), "+f"(c[3])
        : "r"(a[0]), "r"(a[1]), "r"(a[2]), "r"(a[3]), "r"(b[0]), "r"(b[1]));
}

// split-convert a float4 into hi/lo bf16 quads and store (8B each) at elem offset
__device__ __forceinline__ void store_split(uint16_t* hi, uint16_t* lo, int off, float4 v) {
    __nv_bfloat16 hx = __float2bfloat16(v.x);
    __nv_bfloat16 hy = __float2bfloat16(v.y);
    __nv_bfloat16 hz = __float2bfloat16(v.z);
    __nv_bfloat16 hw = __float2bfloat16(v.w);
    __nv_bfloat162 h01; h01.x = hx; h01.y = hy;
    __nv_bfloat162 h23; h23.x = hz; h23.y = hw;
    uint2 hu; hu.x = *(uint32_t*)&h01; hu.y = *(uint32_t*)&h23;
    *(uint2*)(hi + off) = hu;
    __nv_bfloat162 l01, l23;
    l01.x = __float2bfloat16(v.x - __bfloat162float(hx));
    l01.y = __float2bfloat16(v.y - __bfloat162float(hy));
    l23.x = __float2bfloat16(v.z - __bfloat162float(hz));
    l23.y = __float2bfloat16(v.w - __bfloat162float(hw));
    uint2 lu; lu.x = *(uint32_t*)&l01; lu.y = *(uint32_t*)&l23;
    *(uint2*)(lo + off) = lu;
}

// ---------------- bf16-split tensor-core GEMM ----------------
// C = (A[M,K] * W[N,K]^T + bias[n]) * scale, fp32 in/out, internal bf16 3-mma split.
// 128x128 CTA tile, kc=32, 256 threads (8 warps, 2x4), double-buffered 64KB smem.
// Smem tiles [128][32] bf16 with XOR swizzle: elem(row,k) at
//   row*32 + (((k>>3) ^ ((row>>1)&3))<<3) + (k&7)  -> conflict-free LDSM.
template<bool DUAL, bool GATHER>
__global__ void __launch_bounds__(256, 1)
mma_gemm(const float* __restrict__ A, int lda,
         const float* __restrict__ W, int ldw,
         const float* __restrict__ bias, float scale,
         float* __restrict__ C, int ldc,
         float* __restrict__ C2, int K) {
    extern __shared__ char smem_raw[];
    uint16_t* sAh = (uint16_t*)smem_raw;    // [2][128*32]
    uint16_t* sAl = sAh + 8192;
    uint16_t* sBh = sAl + 8192;
    uint16_t* sBl = sBh + 8192;

    int tid = threadIdx.x;
    int warp = tid >> 5, lane = tid & 31;
    int bx = blockIdx.x, by = blockIdx.y;

    int mw = (warp >> 2) * 64;   // warp M offset in CTA tile
    int nw = (warp & 3) * 32;    // warp N offset

    // ---- gmem load mapping: thread t loads row t>>1, k-half (t&1)*16, 4x float4
    int lr  = tid >> 1;
    int lkq = (tid & 1) * 16;

    const float* Aptr;
    {
        int arow = by * 128 + lr;
        if (GATHER) {
            int b = arow >> 9;
            Aptr = A + ((size_t)(b * SS + g_to_sem[arow])) * lda + lkq;
        } else {
            Aptr = A + (size_t)arow * lda + lkq;
        }
    }
    const float* Bptr = W + (size_t)(bx * 128 + lr) * ldw + lkq;

    // swizzled store offsets for the 4 float4s
    int rx = (lr >> 1) & 3;
    int soff[4];
    #pragma unroll
    for (int i = 0; i < 4; i++) {
        int k = lkq + i * 4;
        soff[i] = lr * 32 + ((((k >> 3) ^ rx) << 3) | (k & 7));
    }

    // ---- ldmatrix lane geometry
    // A x4: mat0 rows m..m+7 @k, mat1 rows m+8..15 @k, mat2 rows m..7 @k+8, mat3 m+8..15 @k+8
    int a_rowl = mw + (lane & 7) + (((lane >> 3) & 1) << 3);
    int a_kc   = (lane >> 4) & 1;          // +1 chunk (8 elems) for mats 2,3
    // B x2: lanes 0-7 -> mat0 rows n..n+7 @k; lanes 8-15 -> mat1 @k+8
    int lb = lane & 15;
    int b_rowl = nw + (lb & 7);
    int b_kc   = (lb >> 3) & 1;

    uint32_t sAh_b = (uint32_t)__cvta_generic_to_shared(sAh);
    uint32_t sAl_b = (uint32_t)__cvta_generic_to_shared(sAl);
    uint32_t sBh_b = (uint32_t)__cvta_generic_to_shared(sBh);
    uint32_t sBl_b = (uint32_t)__cvta_generic_to_shared(sBl);

    float c[4][4][4];
    #pragma unroll
    for (int mi = 0; mi < 4; mi++)
        #pragma unroll
        for (int ni = 0; ni < 4; ni++)
            #pragma unroll
            for (int e = 0; e < 4; e++) c[mi][ni][e] = 0.f;

    float4 avr[4], bvr[4];
    #pragma unroll
    for (int i = 0; i < 4; i++) {
        avr[i] = *(const float4*)(Aptr + i * 4);
        bvr[i] = *(const float4*)(Bptr + i * 4);
    }

    int buf = 0;
    for (int kt = 0; kt < K; kt += 32) {
        int bofs = buf * 4096;
        #pragma unroll
        for (int i = 0; i < 4; i++) {
            store_split(sAh, sAl, bofs + soff[i], avr[i]);
            store_split(sBh, sBl, bofs + soff[i], bvr[i]);
        }
        __syncthreads();

        if (kt + 32 < K) {
            #pragma unroll
            for (int i = 0; i < 4; i++) {
                avr[i] = *(const float4*)(Aptr + kt + 32 + i * 4);
                bvr[i] = *(const float4*)(Bptr + kt + 32 + i * 4);
            }
        }

        #pragma unroll
        for (int ks = 0; ks < 2; ks++) {       // two k16 steps per stage
            uint32_t ah[4][4], al[4][4], bh[4][2], bl[4][2];
            #pragma unroll
            for (int mi = 0; mi < 4; mi++) {
                int row = a_rowl + mi * 16;
                int chunk = (ks * 2 + a_kc) ^ ((row >> 1) & 3);
                uint32_t off = (uint32_t)(bofs + row * 32 + (chunk << 3)) * 2u;
                ldsm4(ah[mi], sAh_b + off);
                ldsm4(al[mi], sAl_b + off);
            }
            #pragma unroll
            for (int ni = 0; ni < 4; ni++) {
                int row = b_rowl + ni * 8;
                int chunk = (ks * 2 + b_kc) ^ ((row >> 1) & 3);
                uint32_t off = (uint32_t)(bofs + row * 32 + (chunk << 3)) * 2u;
                ldsm2(bh[ni], sBh_b + off);
                ldsm2(bl[ni], sBl_b + off);
            }
            #pragma unroll
            for (int mi = 0; mi < 4; mi++)
                #pragma unroll
                for (int ni = 0; ni < 4; ni++) {
                    mma16816(c[mi][ni], ah[mi], bh[ni]);
                    mma16816(c[mi][ni], ah[mi], bl[ni]);
                    mma16816(c[mi][ni], al[mi], bh[ni]);
                }
        }
        buf ^= 1;
        // barrier elision safe: buffer `buf` is rewritten only after the NEXT
        // __syncthreads(), which every thread reaches only after finishing
        // this stage's mma reads (same proof as the verified SIMT kernel).
    }

    // ---- epilogue: C frag thread map: rows l>>2 (+8), cols 2*(l&3)+{0,1}
    int r0 = by * 128 + mw, c0 = bx * 128 + nw;
    #pragma unroll
    for (int mi = 0; mi < 4; mi++) {
        #pragma unroll
        for (int half = 0; half < 2; half++) {
            int r = r0 + mi * 16 + (lane >> 2) + half * 8;
            int bq = r >> 9, lq = r & 511;      // for DUAL scatter
            #pragma unroll
            for (int ni = 0; ni < 4; ni++) {
                int cc = c0 + ni * 8 + (lane & 3) * 2;
                float2 v;
                v.x = (c[mi][ni][half * 2 + 0] + bias[cc])     * scale;
                v.y = (c[mi][ni][half * 2 + 1] + bias[cc + 1]) * scale;
                *(float2*)&C[(size_t)r * ldc + cc] = v;
                if (DUAL) {
                    *(float2*)&C2[((size_t)bq * (LL + 1) + lq + 1) * DD + cc] = v;
                }
            }
        }
    }
}

// ---------------- sparse masked attention (unchanged, verified) ----------------
__global__ void __launch_bounds__(256)
attn_kernel() {
    int m = blockIdx.x;
    int b = m >> 9, l = m & 511;
    int h = threadIdx.x >> 5;
    int lane = threadIdx.x & 31;

    const float* qp = g_Q + (size_t)m * DD + h * DHH + lane * 4;
    float4 q = *(const float4*)qp;

    int s0 = g_to_sem[m];
    int cnt = g_cnt[m];
    bool addSelf = (g_sem_syn[b * SS + s0] != l + 1);

    float mmax = -1e30f, lsum = 0.f;
    float4 acc = make_float4(0.f, 0.f, 0.f, 0.f);

    int start = addSelf ? -1 : 0;
    for (int i = start; i < cnt; i++) {
        int s = (i < 0) ? s0 : g_listF[(size_t)m * SS + i];
        size_t base = ((size_t)(b * SS + s)) * DD + h * DHH + lane * 4;
        float4 kv = *(const float4*)(g_K + base);
        float dot = q.x*kv.x + q.y*kv.y + q.z*kv.z + q.w*kv.w;
        #pragma unroll
        for (int off = 16; off > 0; off >>= 1)
            dot += __shfl_xor_sync(0xffffffffu, dot, off);

        float newm = fmaxf(mmax, dot);
        float corr = __expf(mmax - newm);
        float p = __expf(dot - newm);
        lsum = lsum * corr + p;

        float4 vv = *(const float4*)(g_V + base);
        acc.x = acc.x * corr + p * vv.x;
        acc.y = acc.y * corr + p * vv.y;
        acc.z = acc.z * corr + p * vv.z;
        acc.w = acc.w * corr + p * vv.w;
        mmax = newm;
    }

    float inv = 1.f / lsum;
    float4 outv = make_float4(acc.x*inv, acc.y*inv, acc.z*inv, acc.w*inv);
    *(float4*)(g_ctx + (size_t)m * DD + h * DHH + lane * 4) = outv;
}

// ---------------- launch ----------------
extern "C" void kernel_launch(void* const* d_in, const int* in_sizes, int n_in,
                              void* d_out, int out_size) {
    const float* enc       = (const float*)d_in[0];
    const void*  to_sem    = d_in[1];
    const void*  to_semty  = d_in[2];
    const void*  sem_syn   = d_in[3];
    const float* wq = (const float*)d_in[4];
    const float* bq = (const float*)d_in[5];
    const float* wk = (const float*)d_in[6];
    const float* bk = (const float*)d_in[7];
    const float* wv = (const float*)d_in[8];
    const float* bv = (const float*)d_in[9];
    const float* wo = (const float*)d_in[10];
    const float* bo = (const float*)d_in[11];
    const float* type_emb  = (const float*)d_in[12];
    const float* w_proj    = (const float*)d_in[13];
    const float* b_proj    = (const float*)d_in[14];
    const float* bias_root = (const float*)d_in[15];

    float* out = (float*)d_out;

    float *p_Q, *p_K, *p_V, *p_ctx, *p_concat;
    int *p_to_sem, *p_to_semty, *p_sem_syn;
    cudaGetSymbolAddress((void**)&p_Q, g_Q);
    cudaGetSymbolAddress((void**)&p_K, g_K);
    cudaGetSymbolAddress((void**)&p_V, g_V);
    cudaGetSymbolAddress((void**)&p_ctx, g_ctx);
    cudaGetSymbolAddress((void**)&p_concat, g_concat);
    cudaGetSymbolAddress((void**)&p_to_sem, g_to_sem);
    cudaGetSymbolAddress((void**)&p_to_semty, g_to_semty);
    cudaGetSymbolAddress((void**)&p_sem_syn, g_sem_syn);

    const int SMEM = 65536;
    cudaFuncSetAttribute(mma_gemm<false, true>,  cudaFuncAttributeMaxDynamicSharedMemorySize, SMEM);
    cudaFuncSetAttribute(mma_gemm<false, false>, cudaFuncAttributeMaxDynamicSharedMemorySize, SMEM);
    cudaFuncSetAttribute(mma_gemm<true,  false>, cudaFuncAttributeMaxDynamicSharedMemorySize, SMEM);

    const float qscale = 0.08838834764831845f;  // 1/sqrt(128)

    // 0) normalize index dtypes
    normalize_idx_kernel<<<(MQ + 255)/256, 256>>>(to_sem, MQ, p_to_sem);
    normalize_idx_kernel<<<(MQ + 255)/256, 256>>>(to_semty, MQ, p_to_semty);
    normalize_idx_kernel<<<(BB*SS + 255)/256, 256>>>(sem_syn, BB*SS, p_sem_syn);

    // 1) mask lists
    clear_cnt_kernel<<<(BB*LL + 255)/256, 256>>>();
    build_lists_kernel<<<(BB*SS + 255)/256, 256>>>();

    // 2) projections (to_sem row gather fused into the Q GEMM's A loads)
    mma_gemm<false, true><<<dim3(DD/128, MQ/128), 256, SMEM>>>(
        enc, DD, wq, DD, bq, qscale, p_Q, DD, nullptr, DD);
    mma_gemm<false, false><<<dim3(DD/128, MKV/128), 256, SMEM>>>(
        enc, DD, wk, DD, bk, 1.f, p_K, DD, nullptr, DD);
    mma_gemm<false, false><<<dim3(DD/128, MKV/128), 256, SMEM>>>(
        enc, DD, wv, DD, bv, 1.f, p_V, DD, nullptr, DD);

    // 3) sparse masked attention
    attn_kernel<<<MQ, 256>>>();

    // 4) output projection -> first 1024 cols of concat buffer
    mma_gemm<false, false><<<dim3(DD/128, MQ/128), 256, SMEM>>>(
        p_ctx, DD, wo, DD, bo, 1.f, p_concat, DPW, nullptr, DD);

    // 5) type embedding -> cols [1024,1280) of concat buffer
    type_fill_kernel<<<MQ, 64>>>(type_emb);

    // 6) final projection; epilogue writes both output tensors
    mma_gemm<true, false><<<dim3(DD/128, MQ/128), 256, SMEM>>>(
        p_concat, DPW, w_proj, DPW, b_proj, 1.f, out, DD, out + OFF2, DPW);

    // 7) root rows of second output
    root_fill_kernel<<<BB, DD>>>(out + OFF2, bias_root);
}